// round 2
// baseline (speedup 1.0000x reference)
#include <cuda_runtime.h>

// InvariantParticleAttention, GB300 (sm_103a).
// Frames are PER-TOKEN, so transforms do NOT cancel in the scores.
// Fused flash attention with per-row 4x4 Lorentz transforms folded into tile loads:
//   q_g = (eta L_q^T eta) q * 1/sqrt(C)   (query row's frame)
//   k_g = (L_k^T eta) k                   (key row's frame)
//   v_g = (eta L_k^T eta) v               (key row's frame)
//   out = L_q out_g                       (epilogue)
// Scalar channels (first 8) pass through all transforms.

namespace {
constexpr int Nn = 1024;
constexpr int Cc = 128;
constexpr int QT = 64;
constexpr int KT = 64;
constexpr int NTHREADS = 256;
constexpr int SMEM_FLOATS = Cc*QT + Cc*KT + KT*Cc + QT*KT; // 28672 floats = 112 KB
}

__global__ __launch_bounds__(NTHREADS, 2)
void ipa_fa_kernel(const float* __restrict__ gq, const float* __restrict__ gk,
                   const float* __restrict__ gv, const float* __restrict__ gL,
                   float* __restrict__ gout)
{
    extern __shared__ float sm[];
    float* Qs = sm;               // [C][QT]  (transposed q_g, scale folded)
    float* Ks = Qs + Cc*QT;       // [C][KT]  (transposed k_g)
    float* Vs = Ks + Cc*KT;       // [KT][C]  (v_g)
    float* Ps = Vs + KT*Cc;       // [QT][KT] (probs)

    const int tid = threadIdx.x;
    const int tx = tid & 15;      // k-col group (4 cols)
    const int ty = tid >> 4;      // q-row group (4 rows)
    const int bh = blockIdx.y;
    const int b  = bh >> 3;       // H == 8
    const int q0 = blockIdx.x * QT;

    const float* qb  = gq + (size_t)bh * Nn * Cc;
    const float* kb  = gk + (size_t)bh * Nn * Cc;
    const float* vbp = gv + (size_t)bh * Nn * Cc;
    const float* Lb  = gL + (size_t)b * Nn * 16;
    float* ob = gout + (size_t)bh * Nn * Cc;

    const float SCALE = 0.08838834764831845f;  // 1/sqrt(128)

    const int lrow  = tid >> 2;   // 0..63 : tile row this thread loads
    const int lpart = tid & 3;    // 0..3  : 32-channel slice

    // channel slice handled by this thread in load phases:
    //   lpart 0: scalars 0..7 + vectors 0..5   (channels 0..31)
    //   lpart p>0: vectors 8p-2 .. 8p+5        (channels 32p..32p+31)
    const int v0   = (lpart == 0) ? 0 : (8*lpart - 2);
    const int nvec = (lpart == 0) ? 6 : 8;

    // ---- load Q tile: q_g = inv(q-row) * q, transposed, * SCALE ----
    {
        const int row = q0 + lrow;
        const float* Lp = Lb + (size_t)row * 16;
        float Lv[16];
        #pragma unroll
        for (int i = 0; i < 4; i++) {
            float4 t = *(const float4*)(Lp + i*4);
            Lv[i*4+0]=t.x; Lv[i*4+1]=t.y; Lv[i*4+2]=t.z; Lv[i*4+3]=t.w;
        }
        // iM[i][j] = sg(i)*sg(j)*L[j][i],  sg = (+,-,-,-)
        float iM[4][4];
        #pragma unroll
        for (int i = 0; i < 4; i++)
            #pragma unroll
            for (int j = 0; j < 4; j++) {
                float s = ((i==0) == (j==0)) ? 1.f : -1.f;
                iM[i][j] = s * Lv[j*4+i];
            }
        const float* src = qb + (size_t)row * Cc;
        if (lpart == 0) {
            float4 a0 = *(const float4*)(src);
            float4 a1 = *(const float4*)(src + 4);
            Qs[0*QT+lrow]=a0.x*SCALE; Qs[1*QT+lrow]=a0.y*SCALE;
            Qs[2*QT+lrow]=a0.z*SCALE; Qs[3*QT+lrow]=a0.w*SCALE;
            Qs[4*QT+lrow]=a1.x*SCALE; Qs[5*QT+lrow]=a1.y*SCALE;
            Qs[6*QT+lrow]=a1.z*SCALE; Qs[7*QT+lrow]=a1.w*SCALE;
        }
        #pragma unroll
        for (int vv = 0; vv < 8; vv++) {
            if (vv >= nvec) break;
            const int ch = 8 + 4*(v0 + vv);
            float4 x = *(const float4*)(src + ch);
            #pragma unroll
            for (int i = 0; i < 4; i++) {
                float y = iM[i][0]*x.x + iM[i][1]*x.y + iM[i][2]*x.z + iM[i][3]*x.w;
                Qs[(ch+i)*QT + lrow] = y * SCALE;
            }
        }
    }

    float acc[4][8];
    #pragma unroll
    for (int r = 0; r < 4; r++)
        #pragma unroll
        for (int j = 0; j < 8; j++) acc[r][j] = 0.f;
    float mr[4] = {-1e30f, -1e30f, -1e30f, -1e30f};
    float lr[4] = {0.f, 0.f, 0.f, 0.f};

    for (int kt = 0; kt < Nn / KT; kt++) {
        __syncthreads();   // previous PV reads of Ks/Vs/Ps done

        // ---- load K + V tiles with key-row frame transforms ----
        {
            const int kg = kt*KT + lrow;
            const float* Lp = Lb + (size_t)kg * 16;
            float Lv[16];
            #pragma unroll
            for (int i = 0; i < 4; i++) {
                float4 t = *(const float4*)(Lp + i*4);
                Lv[i*4+0]=t.x; Lv[i*4+1]=t.y; Lv[i*4+2]=t.z; Lv[i*4+3]=t.w;
            }
            float iM[4][4], kM[4][4];
            #pragma unroll
            for (int i = 0; i < 4; i++)
                #pragma unroll
                for (int j = 0; j < 4; j++) {
                    float sj = (j==0) ? 1.f : -1.f;
                    float si = (i==0) ? 1.f : -1.f;
                    kM[i][j] = sj * Lv[j*4+i];          // (L^T eta)[i][j]
                    iM[i][j] = si * kM[i][j];           // (eta L^T eta)[i][j]
                }
            const float* ksrc = kb  + (size_t)kg * Cc;
            const float* vsrc = vbp + (size_t)kg * Cc;
            float* vdst = Vs + lrow * Cc;
            if (lpart == 0) {
                float4 a0 = *(const float4*)(ksrc);
                float4 a1 = *(const float4*)(ksrc + 4);
                Ks[0*KT+lrow]=a0.x; Ks[1*KT+lrow]=a0.y;
                Ks[2*KT+lrow]=a0.z; Ks[3*KT+lrow]=a0.w;
                Ks[4*KT+lrow]=a1.x; Ks[5*KT+lrow]=a1.y;
                Ks[6*KT+lrow]=a1.z; Ks[7*KT+lrow]=a1.w;
                float4 b0 = *(const float4*)(vsrc);
                float4 b1 = *(const float4*)(vsrc + 4);
                *(float4*)(vdst)     = b0;
                *(float4*)(vdst + 4) = b1;
            }
            #pragma unroll
            for (int vv = 0; vv < 8; vv++) {
                if (vv >= nvec) break;
                const int ch = 8 + 4*(v0 + vv);
                float4 xk = *(const float4*)(ksrc + ch);
                #pragma unroll
                for (int i = 0; i < 4; i++)
                    Ks[(ch+i)*KT + lrow] =
                        kM[i][0]*xk.x + kM[i][1]*xk.y + kM[i][2]*xk.z + kM[i][3]*xk.w;
                float4 xv = *(const float4*)(vsrc + ch);
                #pragma unroll
                for (int i = 0; i < 4; i++)
                    vdst[ch+i] =
                        iM[i][0]*xv.x + iM[i][1]*xv.y + iM[i][2]*xv.z + iM[i][3]*xv.w;
            }
        }
        __syncthreads();

        // ---- S = Qs^T Ks : 4x4 per thread ----
        float S[4][4];
        #pragma unroll
        for (int r = 0; r < 4; r++)
            #pragma unroll
            for (int j = 0; j < 4; j++) S[r][j] = 0.f;
        #pragma unroll 8
        for (int c = 0; c < Cc; c++) {
            float4 qv = *(const float4*)(Qs + c*QT + ty*4);
            float4 kv = *(const float4*)(Ks + c*KT + tx*4);
            float qa[4] = {qv.x, qv.y, qv.z, qv.w};
            float ka[4] = {kv.x, kv.y, kv.z, kv.w};
            #pragma unroll
            for (int r = 0; r < 4; r++)
                #pragma unroll
                for (int j = 0; j < 4; j++)
                    S[r][j] = fmaf(qa[r], ka[j], S[r][j]);
        }

        // ---- online softmax (rows shared across the 16-lane tx group) ----
        #pragma unroll
        for (int r = 0; r < 4; r++) {
            float rm = fmaxf(fmaxf(S[r][0], S[r][1]), fmaxf(S[r][2], S[r][3]));
            #pragma unroll
            for (int o = 8; o > 0; o >>= 1)
                rm = fmaxf(rm, __shfl_xor_sync(0xffffffffu, rm, o));
            float nm = fmaxf(mr[r], rm);
            float alpha = __expf(mr[r] - nm);
            mr[r] = nm;
            float rs = 0.f;
            #pragma unroll
            for (int j = 0; j < 4; j++) {
                float p = __expf(S[r][j] - nm);
                Ps[(ty*4 + r)*KT + tx*4 + j] = p;
                rs += p;
            }
            #pragma unroll
            for (int o = 8; o > 0; o >>= 1)
                rs += __shfl_xor_sync(0xffffffffu, rs, o);
            lr[r] = lr[r]*alpha + rs;
            #pragma unroll
            for (int j = 0; j < 8; j++) acc[r][j] *= alpha;
        }
        __syncthreads();

        // ---- acc += P @ Vs : 4 rows x 8 cols per thread ----
        #pragma unroll 4
        for (int kk = 0; kk < KT; kk++) {
            float4 va  = *(const float4*)(Vs + kk*Cc + tx*8);
            float4 vb4 = *(const float4*)(Vs + kk*Cc + tx*8 + 4);
            float pa[4];
            #pragma unroll
            for (int r = 0; r < 4; r++)
                pa[r] = Ps[(ty*4 + r)*KT + kk];
            #pragma unroll
            for (int r = 0; r < 4; r++) {
                acc[r][0] = fmaf(pa[r], va.x,  acc[r][0]);
                acc[r][1] = fmaf(pa[r], va.y,  acc[r][1]);
                acc[r][2] = fmaf(pa[r], va.z,  acc[r][2]);
                acc[r][3] = fmaf(pa[r], va.w,  acc[r][3]);
                acc[r][4] = fmaf(pa[r], vb4.x, acc[r][4]);
                acc[r][5] = fmaf(pa[r], vb4.y, acc[r][5]);
                acc[r][6] = fmaf(pa[r], vb4.z, acc[r][6]);
                acc[r][7] = fmaf(pa[r], vb4.w, acc[r][7]);
            }
        }
    }

    // ---- epilogue: normalize, final transform by L (query row), store ----
    #pragma unroll
    for (int r = 0; r < 4; r++) {
        int row = q0 + ty*4 + r;
        float inv = 1.f / lr[r];
        float o[8];
        #pragma unroll
        for (int j = 0; j < 8; j++) o[j] = acc[r][j] * inv;
        if (tx > 0) {
            // cols [8*tx, 8*tx+8) = two complete 4-vectors; transform by L[b,row]
            const float* Lp = Lb + (size_t)row * 16;
            float Lq[16];
            #pragma unroll
            for (int i = 0; i < 4; i++) {
                float4 t = *(const float4*)(Lp + i*4);
                Lq[i*4+0]=t.x; Lq[i*4+1]=t.y; Lq[i*4+2]=t.z; Lq[i*4+3]=t.w;
            }
            float ta[4], tb[4];
            #pragma unroll
            for (int i = 0; i < 4; i++) {
                ta[i] = Lq[i*4+0]*o[0] + Lq[i*4+1]*o[1] + Lq[i*4+2]*o[2] + Lq[i*4+3]*o[3];
                tb[i] = Lq[i*4+0]*o[4] + Lq[i*4+1]*o[5] + Lq[i*4+2]*o[6] + Lq[i*4+3]*o[7];
            }
            #pragma unroll
            for (int i = 0; i < 4; i++) { o[i] = ta[i]; o[4+i] = tb[i]; }
        }
        float4 w0 = make_float4(o[0], o[1], o[2], o[3]);
        float4 w1 = make_float4(o[4], o[5], o[6], o[7]);
        *(float4*)(ob + (size_t)row*Cc + tx*8)     = w0;
        *(float4*)(ob + (size_t)row*Cc + tx*8 + 4) = w1;
    }
}

extern "C" void kernel_launch(void* const* d_in, const int* in_sizes, int n_in,
                              void* d_out, int out_size)
{
    const float* q = (const float*)d_in[0];
    const float* k = (const float*)d_in[1];
    const float* v = (const float*)d_in[2];
    const float* L = (const float*)d_in[3];
    float* out = (float*)d_out;

    size_t smem = (size_t)SMEM_FLOATS * sizeof(float);  // 114688 B
    cudaFuncSetAttribute(ipa_fa_kernel,
                         cudaFuncAttributeMaxDynamicSharedMemorySize, (int)smem);
    dim3 grid(Nn / QT, 64 /* B*H */);
    ipa_fa_kernel<<<grid, NTHREADS, smem>>>(q, k, v, L, out);
}

// round 5
// speedup vs baseline: 2.8363x; 2.8363x over previous
#include <cuda_runtime.h>
#include <cstdint>

#define DI __device__ __forceinline__

DI uint32_t tf32r(float x){ uint32_t r; asm("cvt.rna.tf32.f32 %0, %1;":"=r"(r):"f"(x)); return r; }

DI void mma8(float* c, const uint32_t* a, const uint32_t* b){
    asm volatile("mma.sync.aligned.m16n8k8.row.col.f32.tf32.tf32.f32 "
        "{%0,%1,%2,%3}, {%4,%5,%6,%7}, {%8,%9}, {%0,%1,%2,%3};"
        : "+f"(c[0]),"+f"(c[1]),"+f"(c[2]),"+f"(c[3])
        : "r"(a[0]),"r"(a[1]),"r"(a[2]),"r"(a[3]),"r"(b[0]),"r"(b[1]));
}

namespace {
constexpr int Nn = 1024, Cc = 128, QT = 128, KT = 64;
constexpr int QS_STR = 132, KS_STR = 132, VS_STR = 136, PS_STR = 68;
constexpr int QS_OFF = 0;
constexpr int KS_OFF = QS_OFF + QT*QS_STR;   // 16896
constexpr int VS_OFF = KS_OFF + KT*KS_STR;   // 25344
constexpr int PS_OFF = VS_OFF + KT*VS_STR;   // 34048
constexpr int SA_OFF = PS_OFF + QT*PS_STR;   // 42752
constexpr int SL_OFF = SA_OFF + QT;          // 42880
constexpr int SMEMF  = SL_OFF + QT;          // 43008 floats = 172032 B
constexpr float SCALE = 0.08838834764831845f;  // 1/sqrt(128)
}

__global__ __launch_bounds__(256)
void ipa_mma_kernel(const float* __restrict__ gq, const float* __restrict__ gk,
                    const float* __restrict__ gv, const float* __restrict__ gL,
                    float* __restrict__ gout)
{
    extern __shared__ float sm[];
    uint32_t* Qs = (uint32_t*)(sm + QS_OFF);
    uint32_t* Ks = (uint32_t*)(sm + KS_OFF);
    uint32_t* Vs = (uint32_t*)(sm + VS_OFF);
    uint32_t* Ps = (uint32_t*)(sm + PS_OFF);

    const int tid = threadIdx.x, wid = tid>>5, lane = tid&31;
    const int gid = lane>>2, t4 = lane&3;
    const int bh = blockIdx.y, b = bh>>3;
    const int q0 = blockIdx.x * QT;

    const float* qb = gq + (size_t)bh * Nn * Cc;
    const float* kb = gk + (size_t)bh * Nn * Cc;
    const float* vb = gv + (size_t)bh * Nn * Cc;
    const float* Lb = gL + (size_t)b * Nn * 16;
    float* ob = gout + (size_t)bh * Nn * Cc;

    // ---- Q tile: q_g = (eta L^T eta) q * SCALE -> tf32, row-major [128][132] ----
    {
        const int row = tid>>1, half = tid&1;
        const float* Lp = Lb + (size_t)(q0 + row) * 16;
        float Lv[16];
        #pragma unroll
        for (int i = 0; i < 4; i++){ float4 t = *(const float4*)(Lp + i*4);
            Lv[i*4+0]=t.x; Lv[i*4+1]=t.y; Lv[i*4+2]=t.z; Lv[i*4+3]=t.w; }
        float iM[4][4];
        #pragma unroll
        for (int i = 0; i < 4; i++)
            #pragma unroll
            for (int j = 0; j < 4; j++){
                float s = ((i==0) == (j==0)) ? 1.f : -1.f;
                iM[i][j] = s * Lv[j*4+i];
            }
        const float* src = qb + (size_t)(q0 + row) * Cc;
        uint32_t* dst = Qs + row * QS_STR;
        if (half == 0){
            float4 a0 = *(const float4*)(src);
            float4 a1 = *(const float4*)(src + 4);
            dst[0]=tf32r(a0.x*SCALE); dst[1]=tf32r(a0.y*SCALE);
            dst[2]=tf32r(a0.z*SCALE); dst[3]=tf32r(a0.w*SCALE);
            dst[4]=tf32r(a1.x*SCALE); dst[5]=tf32r(a1.y*SCALE);
            dst[6]=tf32r(a1.z*SCALE); dst[7]=tf32r(a1.w*SCALE);
        }
        const int v0 = half ? 14 : 0, nv = half ? 16 : 14;
        #pragma unroll
        for (int v = 0; v < 16; v++){
            if (v >= nv) break;
            const int ch = 8 + 4*(v0 + v);
            float4 x = *(const float4*)(src + ch);
            dst[ch+0]=tf32r((iM[0][0]*x.x+iM[0][1]*x.y+iM[0][2]*x.z+iM[0][3]*x.w)*SCALE);
            dst[ch+1]=tf32r((iM[1][0]*x.x+iM[1][1]*x.y+iM[1][2]*x.z+iM[1][3]*x.w)*SCALE);
            dst[ch+2]=tf32r((iM[2][0]*x.x+iM[2][1]*x.y+iM[2][2]*x.z+iM[2][3]*x.w)*SCALE);
            dst[ch+3]=tf32r((iM[3][0]*x.x+iM[3][1]*x.y+iM[3][2]*x.z+iM[3][3]*x.w)*SCALE);
        }
    }

    // softmax state: warp wid owns S rows srow, srow+8
    const int srow = wid*16 + gid;
    float m0 = -1e30f, m1 = -1e30f, l0 = 0.f, l1 = 0.f;

    // O accum: warp covers rows [32*wm, 32*wm+32), C cols [64*wc, 64*wc+64)
    const int wm = wid & 3, wc = wid >> 2;
    float o[2][8][4];
    #pragma unroll
    for (int mt = 0; mt < 2; mt++)
        #pragma unroll
        for (int nb = 0; nb < 8; nb++)
            #pragma unroll
            for (int j = 0; j < 4; j++) o[mt][nb][j] = 0.f;

    for (int t = 0; t < Nn / KT; t++){
        __syncthreads();   // prev PV done reading Vs/Ps/SA

        // ---- K & V tiles: key-row transforms -> tf32 smem ----
        {
            const int lrow = tid>>2, lpart = tid&3;
            const int kg = t*KT + lrow;
            const float* Lp = Lb + (size_t)kg * 16;
            float Lv[16];
            #pragma unroll
            for (int i = 0; i < 4; i++){ float4 t4v = *(const float4*)(Lp + i*4);
                Lv[i*4+0]=t4v.x; Lv[i*4+1]=t4v.y; Lv[i*4+2]=t4v.z; Lv[i*4+3]=t4v.w; }
            float kM[4][4], iM[4][4];
            #pragma unroll
            for (int i = 0; i < 4; i++)
                #pragma unroll
                for (int j = 0; j < 4; j++){
                    float sj = (j==0) ? 1.f : -1.f;
                    float si = (i==0) ? 1.f : -1.f;
                    kM[i][j] = sj * Lv[j*4+i];      // (L^T eta)
                    iM[i][j] = si * kM[i][j];       // (eta L^T eta)
                }
            const float* ksrc = kb + (size_t)kg * Cc;
            const float* vsrc = vb + (size_t)kg * Cc;
            uint32_t* kdst = Ks + lrow * KS_STR;
            uint32_t* vdst = Vs + lrow * VS_STR;
            if (lpart == 0){
                float4 a0 = *(const float4*)(ksrc);
                float4 a1 = *(const float4*)(ksrc + 4);
                kdst[0]=tf32r(a0.x); kdst[1]=tf32r(a0.y); kdst[2]=tf32r(a0.z); kdst[3]=tf32r(a0.w);
                kdst[4]=tf32r(a1.x); kdst[5]=tf32r(a1.y); kdst[6]=tf32r(a1.z); kdst[7]=tf32r(a1.w);
                float4 b0 = *(const float4*)(vsrc);
                float4 b1 = *(const float4*)(vsrc + 4);
                vdst[0]=tf32r(b0.x); vdst[1]=tf32r(b0.y); vdst[2]=tf32r(b0.z); vdst[3]=tf32r(b0.w);
                vdst[4]=tf32r(b1.x); vdst[5]=tf32r(b1.y); vdst[6]=tf32r(b1.z); vdst[7]=tf32r(b1.w);
            }
            const int v0 = (lpart == 0) ? 0 : (8*lpart - 2);
            const int nv = (lpart == 0) ? 6 : 8;
            #pragma unroll
            for (int v = 0; v < 8; v++){
                if (v >= nv) break;
                const int ch = 8 + 4*(v0 + v);
                float4 xk = *(const float4*)(ksrc + ch);
                kdst[ch+0]=tf32r(kM[0][0]*xk.x+kM[0][1]*xk.y+kM[0][2]*xk.z+kM[0][3]*xk.w);
                kdst[ch+1]=tf32r(kM[1][0]*xk.x+kM[1][1]*xk.y+kM[1][2]*xk.z+kM[1][3]*xk.w);
                kdst[ch+2]=tf32r(kM[2][0]*xk.x+kM[2][1]*xk.y+kM[2][2]*xk.z+kM[2][3]*xk.w);
                kdst[ch+3]=tf32r(kM[3][0]*xk.x+kM[3][1]*xk.y+kM[3][2]*xk.z+kM[3][3]*xk.w);
                float4 xv = *(const float4*)(vsrc + ch);
                vdst[ch+0]=tf32r(iM[0][0]*xv.x+iM[0][1]*xv.y+iM[0][2]*xv.z+iM[0][3]*xv.w);
                vdst[ch+1]=tf32r(iM[1][0]*xv.x+iM[1][1]*xv.y+iM[1][2]*xv.z+iM[1][3]*xv.w);
                vdst[ch+2]=tf32r(iM[2][0]*xv.x+iM[2][1]*xv.y+iM[2][2]*xv.z+iM[2][3]*xv.w);
                vdst[ch+3]=tf32r(iM[3][0]*xv.x+iM[3][1]*xv.y+iM[3][2]*xv.z+iM[3][3]*xv.w);
            }
        }
        __syncthreads();

        // ---- S = Q K^T : warp rows [16*wid, +16), keys [0,64), FULL C=128 ----
        float c[8][4];
        #pragma unroll
        for (int nb = 0; nb < 8; nb++)
            #pragma unroll
            for (int j = 0; j < 4; j++) c[nb][j] = 0.f;
        #pragma unroll
        for (int k8 = 0; k8 < 16; k8++){            // <-- 16 blocks of 8 channels (was 8: the round-4 bug)
            uint32_t a[4];
            const uint32_t* qp = Qs + srow*QS_STR + k8*8 + t4;
            a[0]=qp[0]; a[1]=qp[8*QS_STR]; a[2]=qp[4]; a[3]=qp[8*QS_STR+4];
            #pragma unroll
            for (int nb = 0; nb < 8; nb++){
                uint32_t bb[2];
                const uint32_t* kp = Ks + (nb*8+gid)*KS_STR + k8*8 + t4;
                bb[0]=kp[0]; bb[1]=kp[4];
                mma8(c[nb], a, bb);
            }
        }

        // ---- online softmax: rows srow (c0,c1) and srow+8 (c2,c3) ----
        float mx0 = -1e30f, mx1 = -1e30f;
        #pragma unroll
        for (int nb = 0; nb < 8; nb++){
            mx0 = fmaxf(mx0, fmaxf(c[nb][0], c[nb][1]));
            mx1 = fmaxf(mx1, fmaxf(c[nb][2], c[nb][3]));
        }
        mx0 = fmaxf(mx0, __shfl_xor_sync(0xffffffffu, mx0, 1));
        mx0 = fmaxf(mx0, __shfl_xor_sync(0xffffffffu, mx0, 2));
        mx1 = fmaxf(mx1, __shfl_xor_sync(0xffffffffu, mx1, 1));
        mx1 = fmaxf(mx1, __shfl_xor_sync(0xffffffffu, mx1, 2));
        float nm0 = fmaxf(m0, mx0), nm1 = fmaxf(m1, mx1);
        float al0 = __expf(m0 - nm0), al1 = __expf(m1 - nm1);
        m0 = nm0; m1 = nm1;
        float s0 = 0.f, s1 = 0.f;
        #pragma unroll
        for (int nb = 0; nb < 8; nb++){
            float p00 = __expf(c[nb][0] - nm0);
            float p01 = __expf(c[nb][1] - nm0);
            float p10 = __expf(c[nb][2] - nm1);
            float p11 = __expf(c[nb][3] - nm1);
            s0 += p00 + p01; s1 += p10 + p11;
            uint2 w0 = make_uint2(tf32r(p00), tf32r(p01));
            uint2 w1 = make_uint2(tf32r(p10), tf32r(p11));
            *(uint2*)(Ps + srow*PS_STR     + nb*8 + 2*t4) = w0;
            *(uint2*)(Ps + (srow+8)*PS_STR + nb*8 + 2*t4) = w1;
        }
        s0 += __shfl_xor_sync(0xffffffffu, s0, 1);
        s0 += __shfl_xor_sync(0xffffffffu, s0, 2);
        s1 += __shfl_xor_sync(0xffffffffu, s1, 1);
        s1 += __shfl_xor_sync(0xffffffffu, s1, 2);
        l0 = l0*al0 + s0; l1 = l1*al1 + s1;
        if (t4 == 0){ sm[SA_OFF + srow] = al0; sm[SA_OFF + srow + 8] = al1; }
        __syncthreads();

        // ---- O = diag(alpha) O + P V : rows [32wm,+32), C [64wc,+64) ----
        float al[2][2];
        al[0][0] = sm[SA_OFF + wm*32 + gid];
        al[0][1] = sm[SA_OFF + wm*32 + gid + 8];
        al[1][0] = sm[SA_OFF + wm*32 + gid + 16];
        al[1][1] = sm[SA_OFF + wm*32 + gid + 24];
        #pragma unroll
        for (int mt = 0; mt < 2; mt++)
            #pragma unroll
            for (int nb = 0; nb < 8; nb++){
                o[mt][nb][0] *= al[mt][0]; o[mt][nb][1] *= al[mt][0];
                o[mt][nb][2] *= al[mt][1]; o[mt][nb][3] *= al[mt][1];
            }
        #pragma unroll
        for (int k8 = 0; k8 < 8; k8++){             // k-dim = 64 keys: 8 blocks (correct)
            uint32_t pa[2][4];
            #pragma unroll
            for (int mt = 0; mt < 2; mt++){
                const uint32_t* pp = Ps + (wm*32 + mt*16 + gid)*PS_STR + k8*8 + t4;
                pa[mt][0]=pp[0]; pa[mt][1]=pp[8*PS_STR]; pa[mt][2]=pp[4]; pa[mt][3]=pp[8*PS_STR+4];
            }
            #pragma unroll
            for (int nb = 0; nb < 8; nb++){
                uint32_t bb[2];
                const uint32_t* vp = Vs + (k8*8+t4)*VS_STR + wc*64 + nb*8 + gid;
                bb[0]=vp[0]; bb[1]=vp[4*VS_STR];
                mma8(o[0][nb], pa[0], bb);
                mma8(o[1][nb], pa[1], bb);
            }
        }
    }

    if (t4 == 0){ sm[SL_OFF + srow] = l0; sm[SL_OFF + srow + 8] = l1; }

    // ---- stage O into Qs region (fp32 row-major [128][132]) ----
    __syncthreads();   // all PV done; Qs no longer needed as tf32 Q
    float* Of = sm + QS_OFF;
    #pragma unroll
    for (int mt = 0; mt < 2; mt++)
        #pragma unroll
        for (int nb = 0; nb < 8; nb++){
            const int r = wm*32 + mt*16 + gid;
            const int col = wc*64 + nb*8 + 2*t4;
            *(float2*)(Of + r*QS_STR + col)     = make_float2(o[mt][nb][0], o[mt][nb][1]);
            *(float2*)(Of + (r+8)*QS_STR + col) = make_float2(o[mt][nb][2], o[mt][nb][3]);
        }
    __syncthreads();

    // ---- epilogue: O/l, transform by L (query row), store ----
    {
        const int row = tid>>1, half = tid&1;
        const int rowg = q0 + row;
        const float invl = 1.f / sm[SL_OFF + row];
        const float* Lp = Lb + (size_t)rowg * 16;
        float Lq[16];
        #pragma unroll
        for (int i = 0; i < 4; i++){ float4 t4v = *(const float4*)(Lp + i*4);
            Lq[i*4+0]=t4v.x; Lq[i*4+1]=t4v.y; Lq[i*4+2]=t4v.z; Lq[i*4+3]=t4v.w; }
        const float* srow_p = Of + row * QS_STR + half*64;
        float* orow = ob + (size_t)rowg * Cc + half*64;
        #pragma unroll
        for (int g = 0; g < 16; g++){
            const int ch = half*64 + g*4;
            float4 x = *(const float4*)(srow_p + g*4);
            x.x *= invl; x.y *= invl; x.z *= invl; x.w *= invl;
            float4 y;
            if (ch < 8){
                y = x;
            } else {
                y.x = Lq[ 0]*x.x + Lq[ 1]*x.y + Lq[ 2]*x.z + Lq[ 3]*x.w;
                y.y = Lq[ 4]*x.x + Lq[ 5]*x.y + Lq[ 6]*x.z + Lq[ 7]*x.w;
                y.z = Lq[ 8]*x.x + Lq[ 9]*x.y + Lq[10]*x.z + Lq[11]*x.w;
                y.w = Lq[12]*x.x + Lq[13]*x.y + Lq[14]*x.z + Lq[15]*x.w;
            }
            *(float4*)(orow + g*4) = y;
        }
    }
}

extern "C" void kernel_launch(void* const* d_in, const int* in_sizes, int n_in,
                              void* d_out, int out_size)
{
    const float* q = (const float*)d_in[0];
    const float* k = (const float*)d_in[1];
    const float* v = (const float*)d_in[2];
    const float* L = (const float*)d_in[3];
    float* out = (float*)d_out;

    size_t smem = (size_t)SMEMF * sizeof(float);   // 172032 B
    cudaFuncSetAttribute(ipa_mma_kernel,
                         cudaFuncAttributeMaxDynamicSharedMemorySize, (int)smem);
    dim3 grid(Nn / QT, 64 /* B*H */);
    ipa_mma_kernel<<<grid, 256, smem>>>(q, k, v, L, out);
}

// round 6
// speedup vs baseline: 2.8365x; 1.0001x over previous
#include <cuda_runtime.h>
#include <cstdint>

#define DI __device__ __forceinline__

DI uint32_t tf32r(float x){ uint32_t r; asm("cvt.rna.tf32.f32 %0, %1;":"=r"(r):"f"(x)); return r; }

DI void mma8(float* c, const uint32_t* a, const uint32_t* b){
    asm volatile("mma.sync.aligned.m16n8k8.row.col.f32.tf32.tf32.f32 "
        "{%0,%1,%2,%3}, {%4,%5,%6,%7}, {%8,%9}, {%0,%1,%2,%3};"
        : "+f"(c[0]),"+f"(c[1]),"+f"(c[2]),"+f"(c[3])
        : "r"(a[0]),"r"(a[1]),"r"(a[2]),"r"(a[3]),"r"(b[0]),"r"(b[1]));
}

namespace {
constexpr int Nn = 1024, Cc = 128, QT = 128, KT = 64;
constexpr int QS_STR = 132, KS_STR = 132, VS_STR = 136, PS_STR = 68;
constexpr int QS_OFF = 0;
constexpr int KS_OFF = QS_OFF + QT*QS_STR;   // 16896
constexpr int VS_OFF = KS_OFF + KT*KS_STR;   // 25344
constexpr int PS_OFF = VS_OFF + KT*VS_STR;   // 34048
constexpr int SA_OFF = PS_OFF + QT*PS_STR;   // 42752
constexpr int SL_OFF = SA_OFF + QT;          // 42880
constexpr int SMEMF  = SL_OFF + QT;          // 43008 floats = 172032 B
constexpr float SCALE = 0.08838834764831845f;  // 1/sqrt(128)
}

__global__ __launch_bounds__(256)
void ipa_mma_kernel(const float* __restrict__ gq, const float* __restrict__ gk,
                    const float* __restrict__ gv, const float* __restrict__ gL,
                    float* __restrict__ gout)
{
    extern __shared__ float sm[];
    uint32_t* Qs = (uint32_t*)(sm + QS_OFF);
    uint32_t* Ks = (uint32_t*)(sm + KS_OFF);
    uint32_t* Vs = (uint32_t*)(sm + VS_OFF);
    uint32_t* Ps = (uint32_t*)(sm + PS_OFF);

    const int tid = threadIdx.x, wid = tid>>5, lane = tid&31;
    const int gid = lane>>2, t4 = lane&3;
    const int bh = blockIdx.y, b = bh>>3;
    const int q0 = blockIdx.x * QT;

    const float* qb = gq + (size_t)bh * Nn * Cc;
    const float* kb = gk + (size_t)bh * Nn * Cc;
    const float* vb = gv + (size_t)bh * Nn * Cc;
    const float* Lb = gL + (size_t)b * Nn * 16;
    float* ob = gout + (size_t)bh * Nn * Cc;

    // ---- Q tile: q_g = (eta L^T eta) q * SCALE -> tf32, row-major [128][132] ----
    {
        const int row = tid>>1, half = tid&1;
        const float* Lp = Lb + (size_t)(q0 + row) * 16;
        float Lv[16];
        #pragma unroll
        for (int i = 0; i < 4; i++){ float4 t = *(const float4*)(Lp + i*4);
            Lv[i*4+0]=t.x; Lv[i*4+1]=t.y; Lv[i*4+2]=t.z; Lv[i*4+3]=t.w; }
        float iM[4][4];
        #pragma unroll
        for (int i = 0; i < 4; i++)
            #pragma unroll
            for (int j = 0; j < 4; j++){
                float s = ((i==0) == (j==0)) ? 1.f : -1.f;
                iM[i][j] = s * Lv[j*4+i];
            }
        const float* src = qb + (size_t)(q0 + row) * Cc;
        uint32_t* dst = Qs + row * QS_STR;
        if (half == 0){
            float4 a0 = *(const float4*)(src);
            float4 a1 = *(const float4*)(src + 4);
            dst[0]=tf32r(a0.x*SCALE); dst[1]=tf32r(a0.y*SCALE);
            dst[2]=tf32r(a0.z*SCALE); dst[3]=tf32r(a0.w*SCALE);
            dst[4]=tf32r(a1.x*SCALE); dst[5]=tf32r(a1.y*SCALE);
            dst[6]=tf32r(a1.z*SCALE); dst[7]=tf32r(a1.w*SCALE);
        }
        const int v0 = half ? 14 : 0, nv = half ? 16 : 14;
        #pragma unroll
        for (int v = 0; v < 16; v++){
            if (v >= nv) break;
            const int ch = 8 + 4*(v0 + v);
            float4 x = *(const float4*)(src + ch);
            dst[ch+0]=tf32r((iM[0][0]*x.x+iM[0][1]*x.y+iM[0][2]*x.z+iM[0][3]*x.w)*SCALE);
            dst[ch+1]=tf32r((iM[1][0]*x.x+iM[1][1]*x.y+iM[1][2]*x.z+iM[1][3]*x.w)*SCALE);
            dst[ch+2]=tf32r((iM[2][0]*x.x+iM[2][1]*x.y+iM[2][2]*x.z+iM[2][3]*x.w)*SCALE);
            dst[ch+3]=tf32r((iM[3][0]*x.x+iM[3][1]*x.y+iM[3][2]*x.z+iM[3][3]*x.w)*SCALE);
        }
    }

    // softmax state: warp wid owns S rows srow, srow+8
    const int srow = wid*16 + gid;
    float m0 = -1e30f, m1 = -1e30f, l0 = 0.f, l1 = 0.f;

    // O accum: warp covers rows [32*wm, 32*wm+32), C cols [64*wc, 64*wc+64)
    const int wm = wid & 3, wc = wid >> 2;
    float o[2][8][4];
    #pragma unroll
    for (int mt = 0; mt < 2; mt++)
        #pragma unroll
        for (int nb = 0; nb < 8; nb++)
            #pragma unroll
            for (int j = 0; j < 4; j++) o[mt][nb][j] = 0.f;

    for (int t = 0; t < Nn / KT; t++){
        __syncthreads();   // prev PV done reading Vs/Ps/SA

        // ---- K & V tiles: key-row transforms -> tf32 smem ----
        {
            const int lrow = tid>>2, lpart = tid&3;
            const int kg = t*KT + lrow;
            const float* Lp = Lb + (size_t)kg * 16;
            float Lv[16];
            #pragma unroll
            for (int i = 0; i < 4; i++){ float4 t4v = *(const float4*)(Lp + i*4);
                Lv[i*4+0]=t4v.x; Lv[i*4+1]=t4v.y; Lv[i*4+2]=t4v.z; Lv[i*4+3]=t4v.w; }
            float kM[4][4], iM[4][4];
            #pragma unroll
            for (int i = 0; i < 4; i++)
                #pragma unroll
                for (int j = 0; j < 4; j++){
                    float sj = (j==0) ? 1.f : -1.f;
                    float si = (i==0) ? 1.f : -1.f;
                    kM[i][j] = sj * Lv[j*4+i];      // (L^T eta)
                    iM[i][j] = si * kM[i][j];       // (eta L^T eta)
                }
            const float* ksrc = kb + (size_t)kg * Cc;
            const float* vsrc = vb + (size_t)kg * Cc;
            uint32_t* kdst = Ks + lrow * KS_STR;
            uint32_t* vdst = Vs + lrow * VS_STR;
            if (lpart == 0){
                float4 a0 = *(const float4*)(ksrc);
                float4 a1 = *(const float4*)(ksrc + 4);
                kdst[0]=tf32r(a0.x); kdst[1]=tf32r(a0.y); kdst[2]=tf32r(a0.z); kdst[3]=tf32r(a0.w);
                kdst[4]=tf32r(a1.x); kdst[5]=tf32r(a1.y); kdst[6]=tf32r(a1.z); kdst[7]=tf32r(a1.w);
                float4 b0 = *(const float4*)(vsrc);
                float4 b1 = *(const float4*)(vsrc + 4);
                vdst[0]=tf32r(b0.x); vdst[1]=tf32r(b0.y); vdst[2]=tf32r(b0.z); vdst[3]=tf32r(b0.w);
                vdst[4]=tf32r(b1.x); vdst[5]=tf32r(b1.y); vdst[6]=tf32r(b1.z); vdst[7]=tf32r(b1.w);
            }
            const int v0 = (lpart == 0) ? 0 : (8*lpart - 2);
            const int nv = (lpart == 0) ? 6 : 8;
            #pragma unroll
            for (int v = 0; v < 8; v++){
                if (v >= nv) break;
                const int ch = 8 + 4*(v0 + v);
                float4 xk = *(const float4*)(ksrc + ch);
                kdst[ch+0]=tf32r(kM[0][0]*xk.x+kM[0][1]*xk.y+kM[0][2]*xk.z+kM[0][3]*xk.w);
                kdst[ch+1]=tf32r(kM[1][0]*xk.x+kM[1][1]*xk.y+kM[1][2]*xk.z+kM[1][3]*xk.w);
                kdst[ch+2]=tf32r(kM[2][0]*xk.x+kM[2][1]*xk.y+kM[2][2]*xk.z+kM[2][3]*xk.w);
                kdst[ch+3]=tf32r(kM[3][0]*xk.x+kM[3][1]*xk.y+kM[3][2]*xk.z+kM[3][3]*xk.w);
                float4 xv = *(const float4*)(vsrc + ch);
                vdst[ch+0]=tf32r(iM[0][0]*xv.x+iM[0][1]*xv.y+iM[0][2]*xv.z+iM[0][3]*xv.w);
                vdst[ch+1]=tf32r(iM[1][0]*xv.x+iM[1][1]*xv.y+iM[1][2]*xv.z+iM[1][3]*xv.w);
                vdst[ch+2]=tf32r(iM[2][0]*xv.x+iM[2][1]*xv.y+iM[2][2]*xv.z+iM[2][3]*xv.w);
                vdst[ch+3]=tf32r(iM[3][0]*xv.x+iM[3][1]*xv.y+iM[3][2]*xv.z+iM[3][3]*xv.w);
            }
        }
        __syncthreads();

        // ---- S = Q K^T : warp rows [16*wid, +16), keys [0,64), FULL C=128 ----
        float c[8][4];
        #pragma unroll
        for (int nb = 0; nb < 8; nb++)
            #pragma unroll
            for (int j = 0; j < 4; j++) c[nb][j] = 0.f;
        #pragma unroll
        for (int k8 = 0; k8 < 16; k8++){            // <-- 16 blocks of 8 channels (was 8: the round-4 bug)
            uint32_t a[4];
            const uint32_t* qp = Qs + srow*QS_STR + k8*8 + t4;
            a[0]=qp[0]; a[1]=qp[8*QS_STR]; a[2]=qp[4]; a[3]=qp[8*QS_STR+4];
            #pragma unroll
            for (int nb = 0; nb < 8; nb++){
                uint32_t bb[2];
                const uint32_t* kp = Ks + (nb*8+gid)*KS_STR + k8*8 + t4;
                bb[0]=kp[0]; bb[1]=kp[4];
                mma8(c[nb], a, bb);
            }
        }

        // ---- online softmax: rows srow (c0,c1) and srow+8 (c2,c3) ----
        float mx0 = -1e30f, mx1 = -1e30f;
        #pragma unroll
        for (int nb = 0; nb < 8; nb++){
            mx0 = fmaxf(mx0, fmaxf(c[nb][0], c[nb][1]));
            mx1 = fmaxf(mx1, fmaxf(c[nb][2], c[nb][3]));
        }
        mx0 = fmaxf(mx0, __shfl_xor_sync(0xffffffffu, mx0, 1));
        mx0 = fmaxf(mx0, __shfl_xor_sync(0xffffffffu, mx0, 2));
        mx1 = fmaxf(mx1, __shfl_xor_sync(0xffffffffu, mx1, 1));
        mx1 = fmaxf(mx1, __shfl_xor_sync(0xffffffffu, mx1, 2));
        float nm0 = fmaxf(m0, mx0), nm1 = fmaxf(m1, mx1);
        float al0 = __expf(m0 - nm0), al1 = __expf(m1 - nm1);
        m0 = nm0; m1 = nm1;
        float s0 = 0.f, s1 = 0.f;
        #pragma unroll
        for (int nb = 0; nb < 8; nb++){
            float p00 = __expf(c[nb][0] - nm0);
            float p01 = __expf(c[nb][1] - nm0);
            float p10 = __expf(c[nb][2] - nm1);
            float p11 = __expf(c[nb][3] - nm1);
            s0 += p00 + p01; s1 += p10 + p11;
            uint2 w0 = make_uint2(tf32r(p00), tf32r(p01));
            uint2 w1 = make_uint2(tf32r(p10), tf32r(p11));
            *(uint2*)(Ps + srow*PS_STR     + nb*8 + 2*t4) = w0;
            *(uint2*)(Ps + (srow+8)*PS_STR + nb*8 + 2*t4) = w1;
        }
        s0 += __shfl_xor_sync(0xffffffffu, s0, 1);
        s0 += __shfl_xor_sync(0xffffffffu, s0, 2);
        s1 += __shfl_xor_sync(0xffffffffu, s1, 1);
        s1 += __shfl_xor_sync(0xffffffffu, s1, 2);
        l0 = l0*al0 + s0; l1 = l1*al1 + s1;
        if (t4 == 0){ sm[SA_OFF + srow] = al0; sm[SA_OFF + srow + 8] = al1; }
        __syncthreads();

        // ---- O = diag(alpha) O + P V : rows [32wm,+32), C [64wc,+64) ----
        float al[2][2];
        al[0][0] = sm[SA_OFF + wm*32 + gid];
        al[0][1] = sm[SA_OFF + wm*32 + gid + 8];
        al[1][0] = sm[SA_OFF + wm*32 + gid + 16];
        al[1][1] = sm[SA_OFF + wm*32 + gid + 24];
        #pragma unroll
        for (int mt = 0; mt < 2; mt++)
            #pragma unroll
            for (int nb = 0; nb < 8; nb++){
                o[mt][nb][0] *= al[mt][0]; o[mt][nb][1] *= al[mt][0];
                o[mt][nb][2] *= al[mt][1]; o[mt][nb][3] *= al[mt][1];
            }
        #pragma unroll
        for (int k8 = 0; k8 < 8; k8++){             // k-dim = 64 keys: 8 blocks (correct)
            uint32_t pa[2][4];
            #pragma unroll
            for (int mt = 0; mt < 2; mt++){
                const uint32_t* pp = Ps + (wm*32 + mt*16 + gid)*PS_STR + k8*8 + t4;
                pa[mt][0]=pp[0]; pa[mt][1]=pp[8*PS_STR]; pa[mt][2]=pp[4]; pa[mt][3]=pp[8*PS_STR+4];
            }
            #pragma unroll
            for (int nb = 0; nb < 8; nb++){
                uint32_t bb[2];
                const uint32_t* vp = Vs + (k8*8+t4)*VS_STR + wc*64 + nb*8 + gid;
                bb[0]=vp[0]; bb[1]=vp[4*VS_STR];
                mma8(o[0][nb], pa[0], bb);
                mma8(o[1][nb], pa[1], bb);
            }
        }
    }

    if (t4 == 0){ sm[SL_OFF + srow] = l0; sm[SL_OFF + srow + 8] = l1; }

    // ---- stage O into Qs region (fp32 row-major [128][132]) ----
    __syncthreads();   // all PV done; Qs no longer needed as tf32 Q
    float* Of = sm + QS_OFF;
    #pragma unroll
    for (int mt = 0; mt < 2; mt++)
        #pragma unroll
        for (int nb = 0; nb < 8; nb++){
            const int r = wm*32 + mt*16 + gid;
            const int col = wc*64 + nb*8 + 2*t4;
            *(float2*)(Of + r*QS_STR + col)     = make_float2(o[mt][nb][0], o[mt][nb][1]);
            *(float2*)(Of + (r+8)*QS_STR + col) = make_float2(o[mt][nb][2], o[mt][nb][3]);
        }
    __syncthreads();

    // ---- epilogue: O/l, transform by L (query row), store ----
    {
        const int row = tid>>1, half = tid&1;
        const int rowg = q0 + row;
        const float invl = 1.f / sm[SL_OFF + row];
        const float* Lp = Lb + (size_t)rowg * 16;
        float Lq[16];
        #pragma unroll
        for (int i = 0; i < 4; i++){ float4 t4v = *(const float4*)(Lp + i*4);
            Lq[i*4+0]=t4v.x; Lq[i*4+1]=t4v.y; Lq[i*4+2]=t4v.z; Lq[i*4+3]=t4v.w; }
        const float* srow_p = Of + row * QS_STR + half*64;
        float* orow = ob + (size_t)rowg * Cc + half*64;
        #pragma unroll
        for (int g = 0; g < 16; g++){
            const int ch = half*64 + g*4;
            float4 x = *(const float4*)(srow_p + g*4);
            x.x *= invl; x.y *= invl; x.z *= invl; x.w *= invl;
            float4 y;
            if (ch < 8){
                y = x;
            } else {
                y.x = Lq[ 0]*x.x + Lq[ 1]*x.y + Lq[ 2]*x.z + Lq[ 3]*x.w;
                y.y = Lq[ 4]*x.x + Lq[ 5]*x.y + Lq[ 6]*x.z + Lq[ 7]*x.w;
                y.z = Lq[ 8]*x.x + Lq[ 9]*x.y + Lq[10]*x.z + Lq[11]*x.w;
                y.w = Lq[12]*x.x + Lq[13]*x.y + Lq[14]*x.z + Lq[15]*x.w;
            }
            *(float4*)(orow + g*4) = y;
        }
    }
}

extern "C" void kernel_launch(void* const* d_in, const int* in_sizes, int n_in,
                              void* d_out, int out_size)
{
    const float* q = (const float*)d_in[0];
    const float* k = (const float*)d_in[1];
    const float* v = (const float*)d_in[2];
    const float* L = (const float*)d_in[3];
    float* out = (float*)d_out;

    size_t smem = (size_t)SMEMF * sizeof(float);   // 172032 B
    cudaFuncSetAttribute(ipa_mma_kernel,
                         cudaFuncAttributeMaxDynamicSharedMemorySize, (int)smem);
    dim3 grid(Nn / QT, 64 /* B*H */);
    ipa_mma_kernel<<<grid, 256, smem>>>(q, k, v, L, out);
}

// round 7
// speedup vs baseline: 5.1257x; 1.8071x over previous
#include <cuda_runtime.h>
#include <cstdint>

#define DI __device__ __forceinline__

DI uint32_t tf32r(float x){ uint32_t r; asm("cvt.rna.tf32.f32 %0, %1;":"=r"(r):"f"(x)); return r; }
DI void mma8(float* c, const uint32_t* a, const uint32_t* b){
    asm volatile("mma.sync.aligned.m16n8k8.row.col.f32.tf32.tf32.f32 "
        "{%0,%1,%2,%3}, {%4,%5,%6,%7}, {%8,%9}, {%0,%1,%2,%3};"
        : "+f"(c[0]),"+f"(c[1]),"+f"(c[2]),"+f"(c[3])
        : "r"(a[0]),"r"(a[1]),"r"(a[2]),"r"(a[3]),"r"(b[0]),"r"(b[1]));
}
DI uint32_t smem_u32(const void* p){ uint32_t a;
    asm("{ .reg .u64 t; cvta.to.shared.u64 t, %1; cvt.u32.u64 %0, t; }":"=r"(a):"l"(p)); return a; }
DI void cpa16(uint32_t dst, const void* src){
    asm volatile("cp.async.cg.shared.global [%0], [%1], 16;"::"r"(dst),"l"(src)); }
DI void cpwait(){ asm volatile("cp.async.commit_group;\n\tcp.async.wait_group 0;":::"memory"); }

namespace {
constexpr int Nn = 1024, Cc = 128, QT = 64, KT = 64;
constexpr float SCALE = 0.08838834764831845f;
constexpr int SMEMF = 16384;      // KBuf[0..8191] VBuf[8192..16383] floats
}

__device__ float g_qg[64*1024*128];
__device__ float g_kg[64*1024*128];
__device__ float g_vg[64*1024*128];

// ---------- kernel 1: Lorentz transforms, once ----------
DI void proc16(const float* __restrict__ s, float* __restrict__ d,
               const float M[4][4], float sc, int part){
    #pragma unroll
    for (int g = 0; g < 4; g++){
        float4 x = *(const float4*)(s + g*4); float4 y;
        if (part == 0 && g < 2) y = make_float4(x.x*sc, x.y*sc, x.z*sc, x.w*sc);
        else {
            y.x = (M[0][0]*x.x+M[0][1]*x.y+M[0][2]*x.z+M[0][3]*x.w)*sc;
            y.y = (M[1][0]*x.x+M[1][1]*x.y+M[1][2]*x.z+M[1][3]*x.w)*sc;
            y.z = (M[2][0]*x.x+M[2][1]*x.y+M[2][2]*x.z+M[2][3]*x.w)*sc;
            y.w = (M[3][0]*x.x+M[3][1]*x.y+M[3][2]*x.z+M[3][3]*x.w)*sc;
        }
        uint4 u = make_uint4(tf32r(y.x), tf32r(y.y), tf32r(y.z), tf32r(y.w));
        *(uint4*)(d + g*4) = u;
    }
}

__global__ __launch_bounds__(128)
void ipa_prep(const float* __restrict__ gq, const float* __restrict__ gk,
              const float* __restrict__ gv, const float* __restrict__ gL){
    const int tid = threadIdx.x;
    const int r = blockIdx.x*16 + (tid>>3);   // bh*1024 + n
    const int part = tid & 7;
    const int n = r & 1023, b = r >> 13;
    const float* Lp = gL + ((size_t)(b*1024 + n))*16;
    float Lv[16];
    #pragma unroll
    for (int i = 0; i < 4; i++){ float4 t = *(const float4*)(Lp + i*4);
        Lv[i*4+0]=t.x; Lv[i*4+1]=t.y; Lv[i*4+2]=t.z; Lv[i*4+3]=t.w; }
    float iM[4][4], kM[4][4];
    #pragma unroll
    for (int i = 0; i < 4; i++)
        #pragma unroll
        for (int j = 0; j < 4; j++){
            float sj = (j==0)?1.f:-1.f, si = (i==0)?1.f:-1.f;
            kM[i][j] = sj * Lv[j*4+i];       // (L^T eta)
            iM[i][j] = si * kM[i][j];        // (eta L^T eta)
        }
    const size_t off = (size_t)r*128 + part*16;
    proc16(gq + off, g_qg + off, iM, SCALE, part);
    proc16(gk + off, g_kg + off, kM, 1.f,   part);
    proc16(gv + off, g_vg + off, iM, 1.f,   part);
}

// ---------- kernel 2: flash attention, tf32 mma, reg-resident Q/P ----------
__global__ __launch_bounds__(128)
void ipa_fa(const float* __restrict__ gL, float* __restrict__ gout){
    extern __shared__ float smf[];
    float* KBf = smf;                 // 64x128 K (also Q stage, later O stage)
    float* VBf = smf + 8192;          // 64x128 V (key-slot permuted)
    const uint32_t KB = smem_u32(KBf), VB = smem_u32(VBf);
    const uint32_t* KB32 = (const uint32_t*)KBf;
    const uint32_t* VB32 = (const uint32_t*)VBf;

    const int tid = threadIdx.x, wid = tid>>5, lane = tid&31;
    const int gid = lane>>2, t4 = lane&3;
    const int bh = blockIdx.y, b = bh>>3;
    const int q0 = blockIdx.x * QT;
    const float* kg = g_kg + (size_t)bh*Nn*Cc;
    const float* vg = g_vg + (size_t)bh*Nn*Cc;

    // ---- stage Q tile into KBuf (XOR swizzle), fragments -> regs ----
    {
        const float* qg = g_qg + (size_t)bh*Nn*Cc + (size_t)q0*Cc;
        #pragma unroll
        for (int i = 0; i < 16; i++){
            int c = tid + 128*i;              // 2048 16B chunks
            int row = c>>5, cc4 = (c&31)*4;
            uint32_t col = (uint32_t)cc4 ^ (4u*(uint32_t)(row&7));
            cpa16(KB + (uint32_t)(row*128 + col)*4u, qg + row*128 + cc4);
        }
        cpwait();
    }
    __syncthreads();

    const int srow = wid*16 + gid;            // rows srow, srow+8
    uint32_t qa[16][4];
    {
        const uint32_t xr = 4u*(uint32_t)(srow&7);
        const uint32_t* r0 = KB32 + srow*128;
        const uint32_t* r1 = KB32 + (srow+8)*128;
        #pragma unroll
        for (int k8 = 0; k8 < 16; k8++){
            uint32_t c0 = (uint32_t)(k8*8+t4) ^ xr;
            uint32_t c1 = (uint32_t)(k8*8+t4+4) ^ xr;
            qa[k8][0]=r0[c0]; qa[k8][1]=r1[c0]; qa[k8][2]=r0[c1]; qa[k8][3]=r1[c1];
        }
    }

    float m0=-1e30f, m1=-1e30f, l0=0.f, l1=0.f;
    float o[16][4];
    #pragma unroll
    for (int cb = 0; cb < 16; cb++){ o[cb][0]=0.f; o[cb][1]=0.f; o[cb][2]=0.f; o[cb][3]=0.f; }

    for (int t = 0; t < Nn/KT; t++){
        __syncthreads();
        {   // cp.async K tile; V tile with key-slot permutation
            const float* kt = kg + (size_t)(t*KT)*Cc;
            const float* vt = vg + (size_t)(t*KT)*Cc;
            #pragma unroll
            for (int i = 0; i < 16; i++){
                int c = tid + 128*i;
                int row = c>>5, cc4 = (c&31)*4;
                uint32_t col = (uint32_t)cc4 ^ (4u*(uint32_t)(row&7));
                cpa16(KB + (uint32_t)(row*128 + col)*4u, kt + row*128 + cc4);
            }
            #pragma unroll
            for (int i = 0; i < 16; i++){
                int c = tid + 128*i;
                int row = c>>5, cc4 = (c&31)*4;   // row = actual key
                int j = row & 7;
                int s = (j&1) ? (4 + (j>>1)) : (j>>1);
                int prow = (row & ~7) | s;
                uint32_t col = (uint32_t)cc4 ^ (8u*(uint32_t)(j>>1));
                cpa16(VB + (uint32_t)(prow*128 + col)*4u, vt + row*128 + cc4);
            }
            cpwait();
        }
        __syncthreads();

        // ---- S = Q K^T : rows srow/srow+8, keys 0..63, C=128 ----
        float c[8][4];
        #pragma unroll
        for (int nb = 0; nb < 8; nb++){ c[nb][0]=0.f; c[nb][1]=0.f; c[nb][2]=0.f; c[nb][3]=0.f; }
        const uint32_t xg = 4u*(uint32_t)gid;
        #pragma unroll
        for (int k8 = 0; k8 < 16; k8++){
            uint32_t c0 = (uint32_t)(k8*8+t4) ^ xg;
            uint32_t c1 = (uint32_t)(k8*8+t4+4) ^ xg;
            #pragma unroll
            for (int nb = 0; nb < 8; nb++){
                const uint32_t* kp = KB32 + (nb*8+gid)*128;
                uint32_t bb[2] = { kp[c0], kp[c1] };
                mma8(c[nb], qa[k8], bb);
            }
        }

        // ---- online softmax (register-local; rows shared by 4 lanes) ----
        float mx0=-1e30f, mx1=-1e30f;
        #pragma unroll
        for (int nb = 0; nb < 8; nb++){
            mx0 = fmaxf(mx0, fmaxf(c[nb][0], c[nb][1]));
            mx1 = fmaxf(mx1, fmaxf(c[nb][2], c[nb][3]));
        }
        mx0 = fmaxf(mx0, __shfl_xor_sync(0xffffffffu, mx0, 1));
        mx0 = fmaxf(mx0, __shfl_xor_sync(0xffffffffu, mx0, 2));
        mx1 = fmaxf(mx1, __shfl_xor_sync(0xffffffffu, mx1, 1));
        mx1 = fmaxf(mx1, __shfl_xor_sync(0xffffffffu, mx1, 2));
        float nm0 = fmaxf(m0, mx0), nm1 = fmaxf(m1, mx1);
        float al0 = __expf(m0-nm0), al1 = __expf(m1-nm1);
        m0 = nm0; m1 = nm1;
        float s0 = 0.f, s1 = 0.f;
        #pragma unroll
        for (int nb = 0; nb < 8; nb++){
            c[nb][0] = __expf(c[nb][0]-nm0);
            c[nb][1] = __expf(c[nb][1]-nm0);
            c[nb][2] = __expf(c[nb][2]-nm1);
            c[nb][3] = __expf(c[nb][3]-nm1);
            s0 += c[nb][0] + c[nb][1];
            s1 += c[nb][2] + c[nb][3];
        }
        s0 += __shfl_xor_sync(0xffffffffu, s0, 1);
        s0 += __shfl_xor_sync(0xffffffffu, s0, 2);
        s1 += __shfl_xor_sync(0xffffffffu, s1, 1);
        s1 += __shfl_xor_sync(0xffffffffu, s1, 2);
        l0 = l0*al0 + s0; l1 = l1*al1 + s1;

        // ---- O = diag(alpha)O + P V (P from regs via permuted V layout) ----
        #pragma unroll
        for (int cb = 0; cb < 16; cb++){
            o[cb][0] *= al0; o[cb][1] *= al0; o[cb][2] *= al1; o[cb][3] *= al1;
        }
        const uint32_t xv = 8u*(uint32_t)t4;
        #pragma unroll
        for (int k8 = 0; k8 < 8; k8++){
            uint32_t pa[4] = { tf32r(c[k8][0]), tf32r(c[k8][2]),
                               tf32r(c[k8][1]), tf32r(c[k8][3]) };
            const uint32_t* v0p = VB32 + (k8*8+t4)*128;
            const uint32_t* v1p = VB32 + (k8*8+t4+4)*128;
            #pragma unroll
            for (int cb = 0; cb < 16; cb++){
                uint32_t cc = (uint32_t)(cb*8+gid) ^ xv;
                uint32_t bb[2] = { v0p[cc], v1p[cc] };
                mma8(o[cb], pa, bb);
            }
        }
    }

    // ---- stage normalized O into smem (stride 132), then epilogue ----
    __syncthreads();
    float* Of = smf;
    const float inv0 = 1.f/l0, inv1 = 1.f/l1;
    #pragma unroll
    for (int cb = 0; cb < 16; cb++){
        *(float2*)(Of + srow*132 + cb*8 + 2*t4)     = make_float2(o[cb][0]*inv0, o[cb][1]*inv0);
        *(float2*)(Of + (srow+8)*132 + cb*8 + 2*t4) = make_float2(o[cb][2]*inv1, o[cb][3]*inv1);
    }
    __syncthreads();

    {
        const int row = tid>>1, half = tid&1;
        const int rowg = q0 + row;
        const float* Lp = gL + ((size_t)(b*1024) + rowg)*16;
        float Lq[16];
        #pragma unroll
        for (int i = 0; i < 4; i++){ float4 t4v = *(const float4*)(Lp + i*4);
            Lq[i*4+0]=t4v.x; Lq[i*4+1]=t4v.y; Lq[i*4+2]=t4v.z; Lq[i*4+3]=t4v.w; }
        const float* sp = Of + row*132 + half*64;
        float* orow = gout + ((size_t)bh*Nn + rowg)*Cc + half*64;
        #pragma unroll
        for (int g = 0; g < 16; g++){
            const int ch = half*64 + g*4;
            float4 x = *(const float4*)(sp + g*4);
            float4 y;
            if (ch < 8) y = x;
            else {
                y.x = Lq[ 0]*x.x + Lq[ 1]*x.y + Lq[ 2]*x.z + Lq[ 3]*x.w;
                y.y = Lq[ 4]*x.x + Lq[ 5]*x.y + Lq[ 6]*x.z + Lq[ 7]*x.w;
                y.z = Lq[ 8]*x.x + Lq[ 9]*x.y + Lq[10]*x.z + Lq[11]*x.w;
                y.w = Lq[12]*x.x + Lq[13]*x.y + Lq[14]*x.z + Lq[15]*x.w;
            }
            *(float4*)(orow + g*4) = y;
        }
    }
}

extern "C" void kernel_launch(void* const* d_in, const int* in_sizes, int n_in,
                              void* d_out, int out_size)
{
    const float* q = (const float*)d_in[0];
    const float* k = (const float*)d_in[1];
    const float* v = (const float*)d_in[2];
    const float* L = (const float*)d_in[3];
    float* out = (float*)d_out;

    ipa_prep<<<4096, 128>>>(q, k, v, L);

    size_t smem = (size_t)SMEMF * sizeof(float);   // 65536 B
    cudaFuncSetAttribute(ipa_fa, cudaFuncAttributeMaxDynamicSharedMemorySize, (int)smem);
    dim3 grid(Nn/QT, 64);
    ipa_fa<<<grid, 128, smem>>>(L, out);
}

// round 8
// speedup vs baseline: 6.7862x; 1.3240x over previous
#include <cuda_runtime.h>
#include <cuda_fp16.h>
#include <cstdint>

#define DI __device__ __forceinline__

DI uint32_t h2pack(float lo, float hi){ uint32_t r;
    asm("cvt.rn.f16x2.f32 %0, %1, %2;":"=r"(r):"f"(hi),"f"(lo)); return r; }
DI void mma16(float* c, const uint32_t* a, uint32_t b0, uint32_t b1){
    asm volatile("mma.sync.aligned.m16n8k16.row.col.f32.f16.f16.f32 "
        "{%0,%1,%2,%3}, {%4,%5,%6,%7}, {%8,%9}, {%0,%1,%2,%3};"
        : "+f"(c[0]),"+f"(c[1]),"+f"(c[2]),"+f"(c[3])
        : "r"(a[0]),"r"(a[1]),"r"(a[2]),"r"(a[3]),"r"(b0),"r"(b1));
}
DI uint32_t smem_u32(const void* p){ uint32_t a;
    asm("{ .reg .u64 t; cvta.to.shared.u64 t, %1; cvt.u32.u64 %0, t; }":"=r"(a):"l"(p)); return a; }
DI void cpa16(uint32_t dst, const void* src){
    asm volatile("cp.async.cg.shared.global [%0], [%1], 16;"::"r"(dst),"l"(src)); }
DI void cpcommit(){ asm volatile("cp.async.commit_group;":::"memory"); }
template<int N> DI void cpwaitg(){ asm volatile("cp.async.wait_group %0;"::"n"(N):"memory"); }

namespace {
constexpr int Nn = 1024, Cc = 128, QT = 64, KT = 64;
constexpr float SCALE = 0.08838834764831845f;   // 1/sqrt(128)
}

// fp16 transformed operands. q/k token-major [bh][n][ch]; v channel-major [bh][ch][n].
__device__ __half g_qh[64*1024*128];
__device__ __half g_kh[64*1024*128];
__device__ __half g_vt[64*128*1024];

// ---------------- kernel 1: Lorentz transforms -> fp16, once ----------------
__global__ __launch_bounds__(128)
void ipa_prep(const float* __restrict__ gq, const float* __restrict__ gk,
              const float* __restrict__ gv, const float* __restrict__ gL)
{
    __shared__ __half vs[128*72];     // V staging [ch][token], stride 72
    const int tid = threadIdx.x;
    const int bh = blockIdx.x >> 4;
    const int n0 = (blockIdx.x & 15) * 64;
    const int tok = tid >> 1, half_ = tid & 1;
    const int n = n0 + tok, b = bh >> 3;

    const float* Lp = gL + ((size_t)(b*1024 + n))*16;
    float Lv[16];
    #pragma unroll
    for (int i = 0; i < 4; i++){ float4 t = *(const float4*)(Lp + i*4);
        Lv[i*4+0]=t.x; Lv[i*4+1]=t.y; Lv[i*4+2]=t.z; Lv[i*4+3]=t.w; }
    float kM[4][4], iM[4][4];
    #pragma unroll
    for (int i = 0; i < 4; i++)
        #pragma unroll
        for (int j = 0; j < 4; j++){
            float sj = (j==0)?1.f:-1.f, si = (i==0)?1.f:-1.f;
            kM[i][j] = sj * Lv[j*4+i];       // (L^T eta)
            iM[i][j] = si * kM[i][j];        // (eta L^T eta)
        }

    const size_t ibase = ((size_t)(bh*1024 + n))*128 + half_*64;
    // q: iM, * SCALE (scalars ch<8 pass through * SCALE)
    #pragma unroll
    for (int g = 0; g < 16; g++){
        float4 x = *(const float4*)(gq + ibase + g*4);
        float4 y;
        if (half_ == 0 && g < 2) y = make_float4(x.x,x.y,x.z,x.w);
        else {
            y.x = iM[0][0]*x.x+iM[0][1]*x.y+iM[0][2]*x.z+iM[0][3]*x.w;
            y.y = iM[1][0]*x.x+iM[1][1]*x.y+iM[1][2]*x.z+iM[1][3]*x.w;
            y.z = iM[2][0]*x.x+iM[2][1]*x.y+iM[2][2]*x.z+iM[2][3]*x.w;
            y.w = iM[3][0]*x.x+iM[3][1]*x.y+iM[3][2]*x.z+iM[3][3]*x.w;
        }
        uint2 u = make_uint2(h2pack(y.x*SCALE, y.y*SCALE), h2pack(y.z*SCALE, y.w*SCALE));
        *(uint2*)((__half*)g_qh + ibase + g*4) = u;
    }
    // k: kM
    #pragma unroll
    for (int g = 0; g < 16; g++){
        float4 x = *(const float4*)(gk + ibase + g*4);
        float4 y;
        if (half_ == 0 && g < 2) y = x;
        else {
            y.x = kM[0][0]*x.x+kM[0][1]*x.y+kM[0][2]*x.z+kM[0][3]*x.w;
            y.y = kM[1][0]*x.x+kM[1][1]*x.y+kM[1][2]*x.z+kM[1][3]*x.w;
            y.z = kM[2][0]*x.x+kM[2][1]*x.y+kM[2][2]*x.z+kM[2][3]*x.w;
            y.w = kM[3][0]*x.x+kM[3][1]*x.y+kM[3][2]*x.z+kM[3][3]*x.w;
        }
        uint2 u = make_uint2(h2pack(y.x, y.y), h2pack(y.z, y.w));
        *(uint2*)((__half*)g_kh + ibase + g*4) = u;
    }
    // v: iM -> smem transpose staging
    #pragma unroll
    for (int g = 0; g < 16; g++){
        float4 x = *(const float4*)(gv + ibase + g*4);
        float4 y;
        if (half_ == 0 && g < 2) y = x;
        else {
            y.x = iM[0][0]*x.x+iM[0][1]*x.y+iM[0][2]*x.z+iM[0][3]*x.w;
            y.y = iM[1][0]*x.x+iM[1][1]*x.y+iM[1][2]*x.z+iM[1][3]*x.w;
            y.z = iM[2][0]*x.x+iM[2][1]*x.y+iM[2][2]*x.z+iM[2][3]*x.w;
            y.w = iM[3][0]*x.x+iM[3][1]*x.y+iM[3][2]*x.z+iM[3][3]*x.w;
        }
        const int ch = half_*64 + g*4;
        vs[(ch+0)*72 + tok] = __float2half_rn(y.x);
        vs[(ch+1)*72 + tok] = __float2half_rn(y.y);
        vs[(ch+2)*72 + tok] = __float2half_rn(y.z);
        vs[(ch+3)*72 + tok] = __float2half_rn(y.w);
    }
    __syncthreads();
    // write Vt: [bh][ch][1024 tokens]
    #pragma unroll
    for (int it = 0; it < 8; it++){
        int idx = tid + 128*it;         // 1024 chunks
        int ch = idx >> 3, c8 = idx & 7;
        uint4 u = *(const uint4*)(vs + ch*72 + c8*8);
        *(uint4*)((__half*)g_vt + ((size_t)(bh*128 + ch))*1024 + n0 + c8*8) = u;
    }
}

// ---------------- kernel 2: fp16 flash attention, double-buffered ----------------
// smem halves: buf b: K at b*16384 (64x128), Vt at b*16384+8192... (in bytes: K@b*32768, V@b*32768+16384)
__global__ __launch_bounds__(128)
void ipa_fa(const float* __restrict__ gL, float* __restrict__ gout)
{
    extern __shared__ __half smh[];              // 65536 B
    const uint32_t SB = smem_u32(smh);
    const uint32_t* W = (const uint32_t*)smh;    // word view

    const int tid = threadIdx.x, wid = tid>>5, lane = tid&31;
    const int gid = lane>>2, t4 = lane&3;
    const int bh = blockIdx.y, b = bh>>3;
    const int q0 = blockIdx.x * QT;

    const __half* qh = g_qh + (size_t)bh*Nn*Cc;
    const __half* kh = g_kh + (size_t)bh*Nn*Cc;
    const __half* vt = g_vt + (size_t)bh*Cc*Nn;

    // ---- prologue: Q -> buf1 K area; tile0 -> buf0 ----
    {
        #pragma unroll
        for (int i = 0; i < 8; i++){            // Q: 512 chunks (64 rows x 8... 64x16)
            int idx = tid + 128*i;              // 1024 chunks
            int row = idx >> 4, c = idx & 15;
            uint32_t cp = (uint32_t)(c ^ (row & 7));
            cpa16(SB + 32768u + (uint32_t)row*256u + cp*16u,
                  qh + (size_t)(q0 + row)*128 + c*8);
        }
        cpcommit();
        #pragma unroll
        for (int i = 0; i < 8; i++){            // K tile 0
            int idx = tid + 128*i;
            int row = idx >> 4, c = idx & 15;
            uint32_t cp = (uint32_t)(c ^ (row & 7));
            cpa16(SB + (uint32_t)row*256u + cp*16u, kh + (size_t)row*128 + c*8);
        }
        #pragma unroll
        for (int i = 0; i < 8; i++){            // V tile 0
            int idx = tid + 128*i;
            int ch = idx >> 3, c = idx & 7;
            uint32_t cp = (uint32_t)(c ^ (ch & 7));
            cpa16(SB + 16384u + (uint32_t)ch*128u + cp*16u,
                  vt + (size_t)ch*1024 + c*8);
        }
        cpcommit();
        cpwaitg<1>();          // Q arrived
        __syncthreads();
    }

    // ---- Q fragments -> registers (32 regs) ----
    const int srow = wid*16 + gid;
    uint32_t qa[8][4];
    {
        const uint32_t* Wq = W + 8192;          // buf1 K region in words
        const uint32_t xr = 4u*(uint32_t)(srow & 7);
        const uint32_t* r0 = Wq + srow*64;
        const uint32_t* r1 = Wq + (srow+8)*64;
        #pragma unroll
        for (int k16 = 0; k16 < 8; k16++){
            uint32_t c0 = (uint32_t)(k16*8 + t4) ^ xr;
            uint32_t c1 = (uint32_t)(k16*8 + t4 + 4) ^ xr;
            qa[k16][0]=r0[c0]; qa[k16][1]=r1[c0]; qa[k16][2]=r0[c1]; qa[k16][3]=r1[c1];
        }
    }
    __syncthreads();           // done reading buf1 K before tile1 overwrites it

    float m0=-1e30f, m1=-1e30f, l0=0.f, l1=0.f;
    float o[16][4];
    #pragma unroll
    for (int cb = 0; cb < 16; cb++){ o[cb][0]=0.f; o[cb][1]=0.f; o[cb][2]=0.f; o[cb][3]=0.f; }

    const uint32_t xg = 4u*(uint32_t)gid;

    for (int t = 0; t < Nn/KT; t++){
        const int buf = t & 1;
        if (t + 1 < Nn/KT){                     // prefetch tile t+1 into other buf
            const int nb2 = (t+1) & 1;
            const __half* kt = kh + (size_t)((t+1)*KT)*128;
            const __half* vp = vt + (size_t)((t+1)*KT);
            #pragma unroll
            for (int i = 0; i < 8; i++){
                int idx = tid + 128*i;
                int row = idx >> 4, c = idx & 15;
                uint32_t cp = (uint32_t)(c ^ (row & 7));
                cpa16(SB + (uint32_t)nb2*32768u + (uint32_t)row*256u + cp*16u,
                      kt + (size_t)row*128 + c*8);
            }
            #pragma unroll
            for (int i = 0; i < 8; i++){
                int idx = tid + 128*i;
                int ch = idx >> 3, c = idx & 7;
                uint32_t cp = (uint32_t)(c ^ (ch & 7));
                cpa16(SB + (uint32_t)nb2*32768u + 16384u + (uint32_t)ch*128u + cp*16u,
                      vp + (size_t)ch*1024 + c*8);
            }
            cpcommit();
            cpwaitg<1>();      // tile t complete
        } else {
            cpwaitg<0>();
        }
        __syncthreads();

        // ---- S = Q K^T ----
        const uint32_t* Wk = W + buf*8192;
        float c[8][4];
        #pragma unroll
        for (int nb = 0; nb < 8; nb++){ c[nb][0]=0.f; c[nb][1]=0.f; c[nb][2]=0.f; c[nb][3]=0.f; }
        #pragma unroll
        for (int k16 = 0; k16 < 8; k16++){
            uint32_t c0 = (uint32_t)(k16*8 + t4) ^ xg;
            uint32_t c1 = (uint32_t)(k16*8 + t4 + 4) ^ xg;
            #pragma unroll
            for (int nb = 0; nb < 8; nb++){
                const uint32_t* kp = Wk + (nb*8 + gid)*64;
                mma16(c[nb], qa[k16], kp[c0], kp[c1]);
            }
        }

        // ---- online softmax (register-local) ----
        float mx0=-1e30f, mx1=-1e30f;
        #pragma unroll
        for (int nb = 0; nb < 8; nb++){
            mx0 = fmaxf(mx0, fmaxf(c[nb][0], c[nb][1]));
            mx1 = fmaxf(mx1, fmaxf(c[nb][2], c[nb][3]));
        }
        mx0 = fmaxf(mx0, __shfl_xor_sync(0xffffffffu, mx0, 1));
        mx0 = fmaxf(mx0, __shfl_xor_sync(0xffffffffu, mx0, 2));
        mx1 = fmaxf(mx1, __shfl_xor_sync(0xffffffffu, mx1, 1));
        mx1 = fmaxf(mx1, __shfl_xor_sync(0xffffffffu, mx1, 2));
        float nm0 = fmaxf(m0, mx0), nm1 = fmaxf(m1, mx1);
        float al0 = __expf(m0-nm0), al1 = __expf(m1-nm1);
        m0 = nm0; m1 = nm1;
        float s0 = 0.f, s1 = 0.f;
        #pragma unroll
        for (int nb = 0; nb < 8; nb++){
            c[nb][0] = __expf(c[nb][0]-nm0);
            c[nb][1] = __expf(c[nb][1]-nm0);
            c[nb][2] = __expf(c[nb][2]-nm1);
            c[nb][3] = __expf(c[nb][3]-nm1);
            s0 += c[nb][0] + c[nb][1];
            s1 += c[nb][2] + c[nb][3];
        }
        s0 += __shfl_xor_sync(0xffffffffu, s0, 1);
        s0 += __shfl_xor_sync(0xffffffffu, s0, 2);
        s1 += __shfl_xor_sync(0xffffffffu, s1, 1);
        s1 += __shfl_xor_sync(0xffffffffu, s1, 2);
        l0 = l0*al0 + s0; l1 = l1*al1 + s1;

        // ---- O = diag(alpha) O + P V  (P packed from C fragments, no smem) ----
        #pragma unroll
        for (int cb = 0; cb < 16; cb++){
            o[cb][0] *= al0; o[cb][1] *= al0; o[cb][2] *= al1; o[cb][3] *= al1;
        }
        const uint32_t* Wv = W + buf*8192 + 4096;
        #pragma unroll
        for (int k16 = 0; k16 < 4; k16++){
            uint32_t pa[4] = { h2pack(c[2*k16][0],   c[2*k16][1]),
                               h2pack(c[2*k16][2],   c[2*k16][3]),
                               h2pack(c[2*k16+1][0], c[2*k16+1][1]),
                               h2pack(c[2*k16+1][2], c[2*k16+1][3]) };
            uint32_t c0 = (uint32_t)(k16*8 + t4) ^ xg;
            uint32_t c1 = (uint32_t)(k16*8 + t4 + 4) ^ xg;
            #pragma unroll
            for (int cb = 0; cb < 16; cb++){
                const uint32_t* vp = Wv + (cb*8 + gid)*32;
                mma16(o[cb], pa, vp[c0], vp[c1]);
            }
        }
        __syncthreads();       // done reading buf before it is overwritten (t+2)
    }

    // ---- stage normalized O (fp32, stride 132) and epilogue ----
    float* Of = (float*)smh;
    const float inv0 = 1.f/l0, inv1 = 1.f/l1;
    #pragma unroll
    for (int cb = 0; cb < 16; cb++){
        *(float2*)(Of + srow*132 + cb*8 + 2*t4)     = make_float2(o[cb][0]*inv0, o[cb][1]*inv0);
        *(float2*)(Of + (srow+8)*132 + cb*8 + 2*t4) = make_float2(o[cb][2]*inv1, o[cb][3]*inv1);
    }
    __syncthreads();
    {
        const int row = tid>>1, half_ = tid&1;
        const int rowg = q0 + row;
        const float* Lp = gL + ((size_t)(b*1024) + rowg)*16;
        float Lq[16];
        #pragma unroll
        for (int i = 0; i < 4; i++){ float4 t4v = *(const float4*)(Lp + i*4);
            Lq[i*4+0]=t4v.x; Lq[i*4+1]=t4v.y; Lq[i*4+2]=t4v.z; Lq[i*4+3]=t4v.w; }
        const float* sp = Of + row*132 + half_*64;
        float* orow = gout + ((size_t)bh*Nn + rowg)*Cc + half_*64;
        #pragma unroll
        for (int g = 0; g < 16; g++){
            const int ch = half_*64 + g*4;
            float4 x = *(const float4*)(sp + g*4);
            float4 y;
            if (ch < 8) y = x;
            else {
                y.x = Lq[ 0]*x.x + Lq[ 1]*x.y + Lq[ 2]*x.z + Lq[ 3]*x.w;
                y.y = Lq[ 4]*x.x + Lq[ 5]*x.y + Lq[ 6]*x.z + Lq[ 7]*x.w;
                y.z = Lq[ 8]*x.x + Lq[ 9]*x.y + Lq[10]*x.z + Lq[11]*x.w;
                y.w = Lq[12]*x.x + Lq[13]*x.y + Lq[14]*x.z + Lq[15]*x.w;
            }
            *(float4*)(orow + g*4) = y;
        }
    }
}

extern "C" void kernel_launch(void* const* d_in, const int* in_sizes, int n_in,
                              void* d_out, int out_size)
{
    const float* q = (const float*)d_in[0];
    const float* k = (const float*)d_in[1];
    const float* v = (const float*)d_in[2];
    const float* L = (const float*)d_in[3];
    float* out = (float*)d_out;

    ipa_prep<<<1024, 128>>>(q, k, v, L);

    cudaFuncSetAttribute(ipa_fa, cudaFuncAttributeMaxDynamicSharedMemorySize, 65536);
    dim3 grid(Nn/QT, 64);
    ipa_fa<<<grid, 128, 65536>>>(L, out);
}

// round 9
// speedup vs baseline: 8.4951x; 1.2518x over previous
#include <cuda_runtime.h>
#include <cuda_fp16.h>
#include <cstdint>

#define DI __device__ __forceinline__

DI uint32_t h2pack(float lo, float hi){ uint32_t r;
    asm("cvt.rn.f16x2.f32 %0, %1, %2;":"=r"(r):"f"(hi),"f"(lo)); return r; }
DI float ex2(float x){ float y; asm("ex2.approx.f32 %0, %1;":"=f"(y):"f"(x)); return y; }
DI void mma16(float* c, const uint32_t* a, uint32_t b0, uint32_t b1){
    asm volatile("mma.sync.aligned.m16n8k16.row.col.f32.f16.f16.f32 "
        "{%0,%1,%2,%3}, {%4,%5,%6,%7}, {%8,%9}, {%0,%1,%2,%3};"
        : "+f"(c[0]),"+f"(c[1]),"+f"(c[2]),"+f"(c[3])
        : "r"(a[0]),"r"(a[1]),"r"(a[2]),"r"(a[3]),"r"(b0),"r"(b1));
}
DI uint32_t smem_u32(const void* p){ uint32_t a;
    asm("{ .reg .u64 t; cvta.to.shared.u64 t, %1; cvt.u32.u64 %0, t; }":"=r"(a):"l"(p)); return a; }
DI void cpa16(uint32_t dst, const void* src){
    asm volatile("cp.async.cg.shared.global [%0], [%1], 16;"::"r"(dst),"l"(src)); }
DI void cpcommit(){ asm volatile("cp.async.commit_group;":::"memory"); }
template<int N> DI void cpwaitg(){ asm volatile("cp.async.wait_group %0;"::"n"(N):"memory"); }

namespace {
constexpr int Nn = 1024, Cc = 128, QT = 64, KT = 64;
// Q carries 1/sqrt(128) * log2(e) so softmax can use raw exp2
constexpr float SCALEQ = 0.08838834764831845f * 1.4426950408889634f;
}

__device__ __half g_qh[64*1024*128];
__device__ __half g_kh[64*1024*128];
__device__ __half g_vt[64*128*1024];   // channel-major [bh][ch][n]

// ---------------- kernel 1: Lorentz transforms -> fp16 (coalesced) ----------------
// One warp per token (16 tokens sequentially); one lane per 4-channel group.
__global__ __launch_bounds__(256)
void ipa_prep(const float* __restrict__ gq, const float* __restrict__ gk,
              const float* __restrict__ gv, const float* __restrict__ gL)
{
    __shared__ alignas(16) __half vs[8][128*24];   // per-warp V staging [ch][24]
    const int tid = threadIdx.x, wid = tid>>5, lane = tid&31;
    const int bh = blockIdx.x >> 3;           // 512 blocks: 64 bh x 8
    const int n0 = (blockIdx.x & 7) * 128;    // block covers 128 tokens
    const int b  = bh >> 3;
    const int nw0 = n0 + wid*16;              // warp's 16 tokens
    __half* vsw = vs[wid];
    const int ch = lane*4;

    #pragma unroll 1
    for (int tk = 0; tk < 16; tk++){
        const int n = nw0 + tk;
        const float* Lp = gL + ((size_t)(b*1024 + n))*16;
        float4 L0 = __ldg((const float4*)Lp);
        float4 L1 = __ldg((const float4*)(Lp+4));
        float4 L2 = __ldg((const float4*)(Lp+8));
        float4 L3 = __ldg((const float4*)(Lp+12));
        float Lv[16] = {L0.x,L0.y,L0.z,L0.w, L1.x,L1.y,L1.z,L1.w,
                        L2.x,L2.y,L2.z,L2.w, L3.x,L3.y,L3.z,L3.w};
        float kM[4][4], iM[4][4];
        #pragma unroll
        for (int i = 0; i < 4; i++)
            #pragma unroll
            for (int j = 0; j < 4; j++){
                float sj = (j==0)?1.f:-1.f, si = (i==0)?1.f:-1.f;
                kM[i][j] = sj * Lv[j*4+i];      // (L^T eta)
                iM[i][j] = si * kM[i][j];       // (eta L^T eta)
            }

        const size_t base = ((size_t)(bh*1024 + n))*128 + ch;
        float4 xq = __ldg((const float4*)(gq + base));
        float4 xk = __ldg((const float4*)(gk + base));
        float4 xv = __ldg((const float4*)(gv + base));
        float4 yq, yk, yv;
        if (lane < 2){ yq = xq; yk = xk; yv = xv; }
        else {
            yq.x = iM[0][0]*xq.x+iM[0][1]*xq.y+iM[0][2]*xq.z+iM[0][3]*xq.w;
            yq.y = iM[1][0]*xq.x+iM[1][1]*xq.y+iM[1][2]*xq.z+iM[1][3]*xq.w;
            yq.z = iM[2][0]*xq.x+iM[2][1]*xq.y+iM[2][2]*xq.z+iM[2][3]*xq.w;
            yq.w = iM[3][0]*xq.x+iM[3][1]*xq.y+iM[3][2]*xq.z+iM[3][3]*xq.w;
            yk.x = kM[0][0]*xk.x+kM[0][1]*xk.y+kM[0][2]*xk.z+kM[0][3]*xk.w;
            yk.y = kM[1][0]*xk.x+kM[1][1]*xk.y+kM[1][2]*xk.z+kM[1][3]*xk.w;
            yk.z = kM[2][0]*xk.x+kM[2][1]*xk.y+kM[2][2]*xk.z+kM[2][3]*xk.w;
            yk.w = kM[3][0]*xk.x+kM[3][1]*xk.y+kM[3][2]*xk.z+kM[3][3]*xk.w;
            yv.x = iM[0][0]*xv.x+iM[0][1]*xv.y+iM[0][2]*xv.z+iM[0][3]*xv.w;
            yv.y = iM[1][0]*xv.x+iM[1][1]*xv.y+iM[1][2]*xv.z+iM[1][3]*xv.w;
            yv.z = iM[2][0]*xv.x+iM[2][1]*xv.y+iM[2][2]*xv.z+iM[2][3]*xv.w;
            yv.w = iM[3][0]*xv.x+iM[3][1]*xv.y+iM[3][2]*xv.z+iM[3][3]*xv.w;
        }
        uint2 uq = make_uint2(h2pack(yq.x*SCALEQ, yq.y*SCALEQ),
                              h2pack(yq.z*SCALEQ, yq.w*SCALEQ));
        uint2 uk = make_uint2(h2pack(yk.x, yk.y), h2pack(yk.z, yk.w));
        *(uint2*)((__half*)g_qh + base) = uq;
        *(uint2*)((__half*)g_kh + base) = uk;
        vsw[(ch+0)*24 + tk] = __float2half_rn(yv.x);
        vsw[(ch+1)*24 + tk] = __float2half_rn(yv.y);
        vsw[(ch+2)*24 + tk] = __float2half_rn(yv.z);
        vsw[(ch+3)*24 + tk] = __float2half_rn(yv.w);
    }
    __syncwarp();
    // V writeout: 32B per (ch, 16 tokens) — full sectors
    #pragma unroll
    for (int it = 0; it < 8; it++){
        int idx = lane + 32*it;          // 0..255
        int c = idx >> 1, part = idx & 1;
        uint4 u = *(const uint4*)(vsw + c*24 + part*8);
        *(uint4*)((__half*)g_vt + ((size_t)(bh*128 + c))*1024 + nw0 + part*8) = u;
    }
}

// ---------------- kernel 2: fp16 flash attention, double-buffered ----------------
__global__ __launch_bounds__(128)
void ipa_fa(const float* __restrict__ gL, float* __restrict__ gout)
{
    extern __shared__ __half smh[];              // 65536 B
    const uint32_t SB = smem_u32(smh);
    const uint32_t* W = (const uint32_t*)smh;

    const int tid = threadIdx.x, wid = tid>>5, lane = tid&31;
    const int gid = lane>>2, t4 = lane&3;
    const int bh = blockIdx.y, b = bh>>3;
    const int q0 = blockIdx.x * QT;

    const __half* qh = g_qh + (size_t)bh*Nn*Cc;
    const __half* kh = g_kh + (size_t)bh*Nn*Cc;
    const __half* vt = g_vt + (size_t)bh*Cc*Nn;

    // ---- prologue: Q -> buf1 K area; tile0 -> buf0 ----
    {
        #pragma unroll
        for (int i = 0; i < 8; i++){
            int idx = tid + 128*i;
            int row = idx >> 4, c = idx & 15;
            uint32_t cp = (uint32_t)(c ^ (row & 7));
            cpa16(SB + 32768u + (uint32_t)row*256u + cp*16u,
                  qh + (size_t)(q0 + row)*128 + c*8);
        }
        cpcommit();
        #pragma unroll
        for (int i = 0; i < 8; i++){
            int idx = tid + 128*i;
            int row = idx >> 4, c = idx & 15;
            uint32_t cp = (uint32_t)(c ^ (row & 7));
            cpa16(SB + (uint32_t)row*256u + cp*16u, kh + (size_t)row*128 + c*8);
        }
        #pragma unroll
        for (int i = 0; i < 8; i++){
            int idx = tid + 128*i;
            int ch = idx >> 3, c = idx & 7;
            uint32_t cp = (uint32_t)(c ^ (ch & 7));
            cpa16(SB + 16384u + (uint32_t)ch*128u + cp*16u,
                  vt + (size_t)ch*1024 + c*8);
        }
        cpcommit();
        cpwaitg<1>();
        __syncthreads();
    }

    const int srow = wid*16 + gid;
    uint32_t qa[8][4];
    {
        const uint32_t* Wq = W + 8192;
        const uint32_t xr = 4u*(uint32_t)(srow & 7);
        const uint32_t* r0 = Wq + srow*64;
        const uint32_t* r1 = Wq + (srow+8)*64;
        #pragma unroll
        for (int k16 = 0; k16 < 8; k16++){
            uint32_t c0 = (uint32_t)(k16*8 + t4) ^ xr;
            uint32_t c1 = (uint32_t)(k16*8 + t4 + 4) ^ xr;
            qa[k16][0]=r0[c0]; qa[k16][1]=r1[c0]; qa[k16][2]=r0[c1]; qa[k16][3]=r1[c1];
        }
    }
    __syncthreads();

    float m0=-1e30f, m1=-1e30f, l0=0.f, l1=0.f;
    float o[16][4];
    #pragma unroll
    for (int cb = 0; cb < 16; cb++){ o[cb][0]=0.f; o[cb][1]=0.f; o[cb][2]=0.f; o[cb][3]=0.f; }

    const uint32_t xg = 4u*(uint32_t)gid;

    for (int t = 0; t < Nn/KT; t++){
        const int buf = t & 1;
        if (t + 1 < Nn/KT){
            const int nb2 = (t+1) & 1;
            const __half* kt = kh + (size_t)((t+1)*KT)*128;
            const __half* vp = vt + (size_t)((t+1)*KT);
            #pragma unroll
            for (int i = 0; i < 8; i++){
                int idx = tid + 128*i;
                int row = idx >> 4, c = idx & 15;
                uint32_t cp = (uint32_t)(c ^ (row & 7));
                cpa16(SB + (uint32_t)nb2*32768u + (uint32_t)row*256u + cp*16u,
                      kt + (size_t)row*128 + c*8);
            }
            #pragma unroll
            for (int i = 0; i < 8; i++){
                int idx = tid + 128*i;
                int ch = idx >> 3, c = idx & 7;
                uint32_t cp = (uint32_t)(c ^ (ch & 7));
                cpa16(SB + (uint32_t)nb2*32768u + 16384u + (uint32_t)ch*128u + cp*16u,
                      vp + (size_t)ch*1024 + c*8);
            }
            cpcommit();
            cpwaitg<1>();
        } else {
            cpwaitg<0>();
        }
        __syncthreads();

        // ---- S = Q K^T (scores in log2 units) ----
        const uint32_t* Wk = W + buf*8192;
        float c[8][4];
        #pragma unroll
        for (int nb = 0; nb < 8; nb++){ c[nb][0]=0.f; c[nb][1]=0.f; c[nb][2]=0.f; c[nb][3]=0.f; }
        #pragma unroll
        for (int k16 = 0; k16 < 8; k16++){
            uint32_t c0 = (uint32_t)(k16*8 + t4) ^ xg;
            uint32_t c1 = (uint32_t)(k16*8 + t4 + 4) ^ xg;
            #pragma unroll
            for (int nb = 0; nb < 8; nb++){
                const uint32_t* kp = Wk + (nb*8 + gid)*64;
                mma16(c[nb], qa[k16], kp[c0], kp[c1]);
            }
        }

        // ---- online softmax (exp2 domain, register-local) ----
        float mx0=-1e30f, mx1=-1e30f;
        #pragma unroll
        for (int nb = 0; nb < 8; nb++){
            mx0 = fmaxf(mx0, fmaxf(c[nb][0], c[nb][1]));
            mx1 = fmaxf(mx1, fmaxf(c[nb][2], c[nb][3]));
        }
        mx0 = fmaxf(mx0, __shfl_xor_sync(0xffffffffu, mx0, 1));
        mx0 = fmaxf(mx0, __shfl_xor_sync(0xffffffffu, mx0, 2));
        mx1 = fmaxf(mx1, __shfl_xor_sync(0xffffffffu, mx1, 1));
        mx1 = fmaxf(mx1, __shfl_xor_sync(0xffffffffu, mx1, 2));
        float nm0 = fmaxf(m0, mx0), nm1 = fmaxf(m1, mx1);
        bool same = (nm0 == m0) & (nm1 == m1);
        float al0 = ex2(m0 - nm0), al1 = ex2(m1 - nm1);
        m0 = nm0; m1 = nm1;
        float s0 = 0.f, s1 = 0.f;
        #pragma unroll
        for (int nb = 0; nb < 8; nb++){
            c[nb][0] = ex2(c[nb][0]-nm0);
            c[nb][1] = ex2(c[nb][1]-nm0);
            c[nb][2] = ex2(c[nb][2]-nm1);
            c[nb][3] = ex2(c[nb][3]-nm1);
            s0 += c[nb][0] + c[nb][1];
            s1 += c[nb][2] + c[nb][3];
        }
        s0 += __shfl_xor_sync(0xffffffffu, s0, 1);
        s0 += __shfl_xor_sync(0xffffffffu, s0, 2);
        s1 += __shfl_xor_sync(0xffffffffu, s1, 1);
        s1 += __shfl_xor_sync(0xffffffffu, s1, 2);
        l0 = l0*al0 + s0; l1 = l1*al1 + s1;

        // ---- O = diag(alpha) O + P V (skip rescale when max unchanged) ----
        if (!__all_sync(0xffffffffu, same)){
            #pragma unroll
            for (int cb = 0; cb < 16; cb++){
                o[cb][0] *= al0; o[cb][1] *= al0; o[cb][2] *= al1; o[cb][3] *= al1;
            }
        }
        const uint32_t* Wv = W + buf*8192 + 4096;
        #pragma unroll
        for (int k16 = 0; k16 < 4; k16++){
            uint32_t pa[4] = { h2pack(c[2*k16][0],   c[2*k16][1]),
                               h2pack(c[2*k16][2],   c[2*k16][3]),
                               h2pack(c[2*k16+1][0], c[2*k16+1][1]),
                               h2pack(c[2*k16+1][2], c[2*k16+1][3]) };
            uint32_t c0 = (uint32_t)(k16*8 + t4) ^ xg;
            uint32_t c1 = (uint32_t)(k16*8 + t4 + 4) ^ xg;
            #pragma unroll
            for (int cb = 0; cb < 16; cb++){
                const uint32_t* vp = Wv + (cb*8 + gid)*32;
                mma16(o[cb], pa, vp[c0], vp[c1]);
            }
        }
        __syncthreads();
    }

    // ---- stage normalized O (fp32, stride 132) and epilogue ----
    float* Of = (float*)smh;
    const float inv0 = 1.f/l0, inv1 = 1.f/l1;
    #pragma unroll
    for (int cb = 0; cb < 16; cb++){
        *(float2*)(Of + srow*132 + cb*8 + 2*t4)     = make_float2(o[cb][0]*inv0, o[cb][1]*inv0);
        *(float2*)(Of + (srow+8)*132 + cb*8 + 2*t4) = make_float2(o[cb][2]*inv1, o[cb][3]*inv1);
    }
    __syncthreads();
    {
        const int row = tid>>1, half_ = tid&1;
        const int rowg = q0 + row;
        const float* Lp = gL + ((size_t)(b*1024) + rowg)*16;
        float Lq[16];
        #pragma unroll
        for (int i = 0; i < 4; i++){ float4 t4v = *(const float4*)(Lp + i*4);
            Lq[i*4+0]=t4v.x; Lq[i*4+1]=t4v.y; Lq[i*4+2]=t4v.z; Lq[i*4+3]=t4v.w; }
        const float* sp = Of + row*132 + half_*64;
        float* orow = gout + ((size_t)bh*Nn + rowg)*Cc + half_*64;
        #pragma unroll
        for (int g = 0; g < 16; g++){
            const int ch = half_*64 + g*4;
            float4 x = *(const float4*)(sp + g*4);
            float4 y;
            if (ch < 8) y = x;
            else {
                y.x = Lq[ 0]*x.x + Lq[ 1]*x.y + Lq[ 2]*x.z + Lq[ 3]*x.w;
                y.y = Lq[ 4]*x.x + Lq[ 5]*x.y + Lq[ 6]*x.z + Lq[ 7]*x.w;
                y.z = Lq[ 8]*x.x + Lq[ 9]*x.y + Lq[10]*x.z + Lq[11]*x.w;
                y.w = Lq[12]*x.x + Lq[13]*x.y + Lq[14]*x.z + Lq[15]*x.w;
            }
            *(float4*)(orow + g*4) = y;
        }
    }
}

extern "C" void kernel_launch(void* const* d_in, const int* in_sizes, int n_in,
                              void* d_out, int out_size)
{
    const float* q = (const float*)d_in[0];
    const float* k = (const float*)d_in[1];
    const float* v = (const float*)d_in[2];
    const float* L = (const float*)d_in[3];
    float* out = (float*)d_out;

    ipa_prep<<<512, 256>>>(q, k, v, L);

    cudaFuncSetAttribute(ipa_fa, cudaFuncAttributeMaxDynamicSharedMemorySize, 65536);
    dim3 grid(Nn/QT, 64);
    ipa_fa<<<grid, 128, 65536>>>(L, out);
}